// round 10
// baseline (speedup 1.0000x reference)
#include <cuda_runtime.h>
#include <cuda_fp16.h>
#include <cstdint>

// lct_fk round 10: R7 base (best 184.8us) + three exact op-count cuts:
//  (1) global twiddle table g_TW (LDG.128, L1-resident) replacing the 60-FMA
//      recurrence + sincos per pass,
//  (2) zero-input stage-1 skip (ZIN) where half the FFT input is zero,
//  (3) half-output pruning (HOUT) where only k<128 outputs are consumed.

#define LL 256u
#define VOLS 2

__device__ __half2 g_A[(size_t)VOLS * LL * LL * LL]; // 134 MB
__device__ float2  g_TW[256];                        // w^(j*k) = e^{-2pi i jk/256}

__device__ const int BR4[16] = {0,8,4,12,2,10,6,14,1,9,5,13,3,11,7,15};

__device__ __forceinline__ float2 h2f(__half2 h) { return __half22float2(h); }
__device__ __forceinline__ __half2 f2h(float2 f) { return __floats2half2_rn(f.x, f.y); }

__global__ void k_init_tw() {
    int i = threadIdx.x;                 // 256
    int j = i >> 4, k = i & 15;
    double ang = -6.283185307179586 * (double)(j * k) / 256.0;
    double ds, dc;
    sincos(ang, &ds, &dc);
    g_TW[i] = make_float2((float)dc, (float)ds);
}

// ---------------- 16-pt in-register DIT FFT (input bit-reversed) ------------
// ZIN:  inputs at odd slots are zero -> stage 1 becomes r[odd]=r[even].
// HOUT: only outputs 0..7 needed -> last stage skips the minus half.
template<bool ZIN, bool HOUT>
__device__ __forceinline__ void fft16x(float2 r[16], float dir) {
    const float CT[8] = {1.f, 0.92387953f, 0.70710678f, 0.38268343f,
                         0.f, -0.38268343f, -0.70710678f, -0.92387953f};
    const float ST[8] = {0.f, -0.38268343f, -0.70710678f, -0.92387953f,
                         -1.f, -0.92387953f, -0.70710678f, -0.38268343f};
    // stage 1 (w = 1)
    if (ZIN) {
#pragma unroll
        for (int m = 0; m < 8; ++m) r[2 * m + 1] = r[2 * m];
    } else {
#pragma unroll
        for (int m = 0; m < 8; ++m) {
            float2 a = r[2 * m], b = r[2 * m + 1];
            r[2 * m]     = make_float2(a.x + b.x, a.y + b.y);
            r[2 * m + 1] = make_float2(a.x - b.x, a.y - b.y);
        }
    }
    // stages 2..3
#pragma unroll
    for (int s = 2; s <= 3; ++s) {
        int half = 1 << (s - 1);
#pragma unroll
        for (int j = 0; j < 8; ++j) {
            int k = j & (half - 1);
            int i0 = ((j >> (s - 1)) << s) + k;
            int i1 = i0 + half;
            float cs = CT[k << (4 - s)];
            float sn = dir * ST[k << (4 - s)];
            float2 b = r[i1];
            float tx = b.x * cs - b.y * sn;
            float ty = b.x * sn + b.y * cs;
            float2 a = r[i0];
            r[i1] = make_float2(a.x - tx, a.y - ty);
            r[i0] = make_float2(a.x + tx, a.y + ty);
        }
    }
    // stage 4 (half = 8, k = j)
#pragma unroll
    for (int j = 0; j < 8; ++j) {
        float cs = CT[j];
        float sn = dir * ST[j];
        float2 b = r[j + 8];
        float tx = b.x * cs - b.y * sn;
        float ty = b.x * sn + b.y * cs;
        float2 a = r[j];
        r[j] = make_float2(a.x + tx, a.y + ty);
        if (!HOUT) r[j + 8] = make_float2(a.x - tx, a.y - ty);
    }
}

// Full 256-pt FFT for one line handled by 16 threads (role j).
// Entry: r[BR4[n1]] = x[16*n1 + j] (odd slots may be skipped if ZIN).
// Exit:  r[k2] = X[j + 16*k2] (k2 < 8 only if HOUT).
template<bool ZIN, bool HOUT>
__device__ __forceinline__ void fft256_pass(float2 r[16], float2* Tline,
                                            const float4* __restrict__ tw4,
                                            int j, float dir) {
    fft16x<ZIN, false>(r, dir);
    // inter-pass twiddle from global table (L1-resident, 4x LDG.128 worth)
#pragma unroll
    for (int m = 0; m < 8; ++m) {
        float4 q = tw4[m];                 // twiddles k1 = 2m, 2m+1
        if (m > 0) {
            float wx = q.x, wy = dir * q.y;
            float2 a = r[2 * m];
            r[2 * m] = make_float2(a.x * wx - a.y * wy, a.x * wy + a.y * wx);
        }
        {
            float wx = q.z, wy = dir * q.w;
            float2 a = r[2 * m + 1];
            r[2 * m + 1] = make_float2(a.x * wx - a.y * wy, a.x * wy + a.y * wx);
        }
    }
    __syncthreads();
#pragma unroll
    for (int k1 = 0; k1 < 16; ++k1) Tline[k1 * 17 + j] = r[k1];
    __syncthreads();
    float2 rr[16];
#pragma unroll
    for (int n2 = 0; n2 < 16; ++n2) rr[BR4[n2]] = Tline[j * 17 + n2];
    fft16x<false, HOUT>(rr, dir);
#pragma unroll
    for (int k = 0; k < (HOUT ? 8 : 16); ++k) r[k] = rr[k];
}

// ---------------- Pass 1: preprocess + x-FFT + x-filter ---------------------
__global__ void k_fwd_x(const float* __restrict__ in) {
    __shared__ float2 T[16][273];
    int tid = threadIdx.x;
    int j = tid & 15, ln = tid >> 4;
    unsigned h = blockIdx.x * 16 + ln, t = blockIdx.y, v = blockIdx.z;
    const float4* tw4 = (const float4*)(g_TW + 16 * j);
    float g = (float)t * (1.0f / 127.0f);
    const float* src = in + (((v * 128u + t) * 128u + h) * 128u);
    float2 r[16];
#pragma unroll
    for (int n1 = 0; n1 < 8; ++n1) {
        float f = src[16 * n1 + j];
        float xx = f * g * g;
        float val = (xx > 0.0f) ? sqrtf(xx) : 0.0f;
        r[BR4[n1]] = make_float2(val, 0.0f);
    }
    fft256_pass<true, false>(r, T[ln], tw4, j, 1.0f);
    __syncthreads();
#pragma unroll
    for (int k2 = 0; k2 < 16; ++k2) T[ln][j + 17 * k2] = r[k2]; // pidx(k)=k+(k>>4)
    __syncthreads();
    __half2* __restrict__ dst = g_A + (((v * LL + t) * LL + h) * LL);
#pragma unroll
    for (int k2 = 0; k2 < 16; ++k2) {
        int k = j + 16 * k2;
        float2 a = T[ln][k + (k >> 4)];
        float2 b = make_float2(0.f, 0.f);
        if (k != 128) { int km = (k - 1) & 255; b = T[ln][km + (km >> 4)]; }
        dst[k] = f2h(make_float2(0.5f * (a.x + b.x), 0.5f * (a.y + b.y)));
    }
}

// ---------------- Pass 2: h-FFT (reads h<128) + y-filter, writes all h ------
__global__ void k_fwd_h() {
    __shared__ float2 T[16][273];
    int tid = threadIdx.x;
    int tx = tid & 15, j = tid >> 4;
    unsigned x = blockIdx.x * 16 + tx, t = blockIdx.y, v = blockIdx.z;
    const float4* tw4 = (const float4*)(g_TW + 16 * j);
    unsigned base = (v * LL + t) * LL * LL + x;
    float2 r[16];
#pragma unroll
    for (int n1 = 0; n1 < 8; ++n1) {
        unsigned hh = 16 * n1 + j;
        r[BR4[n1]] = h2f(g_A[base + hh * LL]);
    }
    fft256_pass<true, false>(r, T[tx], tw4, j, 1.0f);
    __syncthreads();
#pragma unroll
    for (int k2 = 0; k2 < 16; ++k2) T[tx][j + 17 * k2] = r[k2];
    __syncthreads();
#pragma unroll
    for (int k2 = 0; k2 < 16; ++k2) {
        int k = j + 16 * k2;
        float2 a = T[tx][k + (k >> 4)];
        float2 b = make_float2(0.f, 0.f);
        if (k != 128) { int km = (k - 1) & 255; b = T[tx][km + (km >> 4)]; }
        g_A[base + (unsigned)k * LL] =
            f2h(make_float2(0.5f * (a.x + b.x), 0.5f * (a.y + b.y)));
    }
}

// ---- Pass 3 (fused): forward t-FFT -> Stolt z-resample -> inverse t-FFT ----
__global__ void k_t_samp() {
    __shared__ float2 T[16][273];
    int tid = threadIdx.x;
    int tx = tid & 15, j = tid >> 4;
    unsigned x = blockIdx.x * 16 + tx, h = blockIdx.y, v = blockIdx.z;
    const float4* tw4 = (const float4*)(g_TW + 16 * j);
    unsigned base = v * LL * LL * LL + h * LL + x;

    float2 r[16];
#pragma unroll
    for (int n1 = 0; n1 < 8; ++n1) {
        unsigned tt = 16 * n1 + j;
        r[BR4[n1]] = h2f(g_A[base + tt * (LL * LL)]);
    }
    fft256_pass<true, true>(r, T[tx], tw4, j, 1.0f); // F[k] for k<128 in r[0..7]

    __syncthreads();
#pragma unroll
    for (int k2 = 0; k2 < 8; ++k2) {
        int k = j + 16 * k2;
        T[tx][k + (k >> 4)] = r[k2];      // stash k<128 spectrum
    }
    __syncthreads();

    int iy = ((int)h + 128) & 255;
    int ixs = ((int)x + 128) & 255;
    float gx = (float)(ixs - 128) * (1.0f / 128.0f);
    float gy = (float)(iy - 128) * (1.0f / 128.0f);
    float rxy = 0.1024f * (gx * gx + gy * gy);

#pragma unroll
    for (int n1 = 0; n1 < 8; ++n1) {      // t = 16*n1+j < 128
        int t = 16 * n1 + j;
        float2 s = make_float2(0.f, 0.f);
        if (t >= 1) {
            float gz = (float)t * (1.0f / 128.0f);
            float q = rxy + gz * gz;       // >= (1/128)^2
            float rq = rsqrtf(q);
            float gzn = q * rq;            // sqrt(q)
            float pzf = 128.0f * gzn + 127.5f;   // >= 128.5
            int z0 = (int)pzf;
            float dz = pzf - (float)z0;
            int p0 = z0 - 128, p1 = z0 - 127;    // p0 >= 0
            float2 S0 = (p0 <= 127) ? T[tx][p0 + (p0 >> 4)] : make_float2(0.f, 0.f);
            float2 S1 = (p1 <= 127) ? T[tx][p1 + (p1 >> 4)] : make_float2(0.f, 0.f);
            float sc = gz * rq;            // ~ gz / gzn
            s = make_float2((S0.x * (1.f - dz) + S1.x * dz) * sc,
                            (S0.y * (1.f - dz) + S1.y * dz) * sc);
        }
        r[BR4[n1]] = s;                    // odd slots (t>=128) are zero -> ZIN
    }
    fft256_pass<true, true>(r, T[tx], tw4, j, -1.0f);

    const float SC = 1.0f / 4096.0f;      // first chunk of 1/2^24
#pragma unroll
    for (int k2 = 0; k2 < 8; ++k2)
        g_A[base + (unsigned)(j + 16 * k2) * (LL * LL)] =
            f2h(make_float2(r[k2].x * SC, r[k2].y * SC));
}

// ---------------- Pass 4: inverse h-FFT (reads all h, writes h<128) ---------
__global__ void k_inv_h() {
    __shared__ float2 T[16][273];
    int tid = threadIdx.x;
    int tx = tid & 15, j = tid >> 4;
    unsigned x = blockIdx.x * 16 + tx, t = blockIdx.y, v = blockIdx.z;
    const float4* tw4 = (const float4*)(g_TW + 16 * j);
    unsigned base = (v * LL + t) * LL * LL + x;
    float2 r[16];
#pragma unroll
    for (int n1 = 0; n1 < 16; ++n1)
        r[BR4[n1]] = h2f(g_A[base + (unsigned)(16 * n1 + j) * LL]);
    fft256_pass<false, true>(r, T[tx], tw4, j, -1.0f);
    const float SC = 1.0f / 4096.0f;      // second chunk of 1/2^24
#pragma unroll
    for (int k2 = 0; k2 < 8; ++k2)
        g_A[base + (unsigned)(j + 16 * k2) * LL] =
            f2h(make_float2(r[k2].x * SC, r[k2].y * SC));
}

// ---------------- Pass 5: inverse x-FFT + real crop ------------------------
__global__ void k_inv_x(float* __restrict__ out) {
    __shared__ float2 T[16][273];
    int tid = threadIdx.x;
    int j = tid & 15, ln = tid >> 4;
    unsigned h = blockIdx.x * 16 + ln, t = blockIdx.y, v = blockIdx.z;
    const float4* tw4 = (const float4*)(g_TW + 16 * j);
    unsigned base = ((v * LL + t) * LL + h) * LL;
    float2 r[16];
#pragma unroll
    for (int n1 = 0; n1 < 16; ++n1)
        r[BR4[n1]] = h2f(g_A[base + 16 * n1 + j]);
    fft256_pass<false, true>(r, T[ln], tw4, j, -1.0f);
    float* dst = out + (((v * 128u + t) * 128u + h) * 128u);
#pragma unroll
    for (int k2 = 0; k2 < 8; ++k2)
        dst[j + 16 * k2] = r[k2].x;       // normalization fully folded upstream
}

extern "C" void kernel_launch(void* const* d_in, const int* in_sizes, int n_in,
                              void* d_out, int out_size) {
    (void)in_sizes; (void)n_in; (void)out_size;
    const float* in = (const float*)d_in[0];
    float* out = (float*)d_out;

    k_init_tw<<<1, 256>>>();
    k_fwd_x<<<dim3(8, 128, VOLS), 256>>>(in);
    k_fwd_h<<<dim3(16, 128, VOLS), 256>>>();
    k_t_samp<<<dim3(16, 256, VOLS), 256>>>();
    k_inv_h<<<dim3(16, 128, VOLS), 256>>>();
    k_inv_x<<<dim3(8, 128, VOLS), 256>>>(out);
}

// round 11
// speedup vs baseline: 1.1719x; 1.1719x over previous
#include <cuda_runtime.h>
#include <cuda_fp16.h>
#include <cstdint>

// lct_fk round 11: exactly round 7 (best: 184.8us / 3.34e-4) plus two
// zero-register-cost op cuts:
//  ZIN : stage-1 butterflies skipped where half the FFT input is zero
//        (fwd x/h passes, both t_samp passes) -> register renames.
//  HOUT: final-stage minus-half skipped where only k<128 outputs are used
//        (t_samp both passes, inv_h, inv_x).
// No twiddle table (R10's float4 hoisting cost 24 regs), no launch bounds.

#define LL 256u
#define VOLS 2

__device__ __half2 g_A[(size_t)VOLS * LL * LL * LL]; // 134 MB

__device__ const int BR4[16] = {0,8,4,12,2,10,6,14,1,9,5,13,3,11,7,15};

__device__ __forceinline__ float2 h2f(__half2 h) { return __half22float2(h); }
__device__ __forceinline__ __half2 f2h(float2 f) { return __floats2half2_rn(f.x, f.y); }

// ---------------- 16-pt in-register DIT FFT (input bit-reversed) ------------
// ZIN:  inputs at odd slots are zero -> stage 1 becomes r[odd]=r[even].
// HOUT: only outputs 0..7 needed -> final stage skips the minus half.
template<bool ZIN, bool HOUT>
__device__ __forceinline__ void fft16x(float2 r[16], float dir) {
    const float CT[8] = {1.f, 0.92387953f, 0.70710678f, 0.38268343f,
                         0.f, -0.38268343f, -0.70710678f, -0.92387953f};
    const float ST[8] = {0.f, -0.38268343f, -0.70710678f, -0.92387953f,
                         -1.f, -0.92387953f, -0.70710678f, -0.38268343f};
    // stage 1 (w = 1)
    if (ZIN) {
#pragma unroll
        for (int m = 0; m < 8; ++m) r[2 * m + 1] = r[2 * m];
    } else {
#pragma unroll
        for (int m = 0; m < 8; ++m) {
            float2 a = r[2 * m], b = r[2 * m + 1];
            r[2 * m]     = make_float2(a.x + b.x, a.y + b.y);
            r[2 * m + 1] = make_float2(a.x - b.x, a.y - b.y);
        }
    }
    // stages 2..3
#pragma unroll
    for (int s = 2; s <= 3; ++s) {
        int half = 1 << (s - 1);
#pragma unroll
        for (int j = 0; j < 8; ++j) {
            int k = j & (half - 1);
            int i0 = ((j >> (s - 1)) << s) + k;
            int i1 = i0 + half;
            float cs = CT[k << (4 - s)];
            float sn = dir * ST[k << (4 - s)];
            float2 b = r[i1];
            float tx = b.x * cs - b.y * sn;
            float ty = b.x * sn + b.y * cs;
            float2 a = r[i0];
            r[i1] = make_float2(a.x - tx, a.y - ty);
            r[i0] = make_float2(a.x + tx, a.y + ty);
        }
    }
    // stage 4 (half = 8, k = j)
#pragma unroll
    for (int j = 0; j < 8; ++j) {
        float cs = CT[j];
        float sn = dir * ST[j];
        float2 b = r[j + 8];
        float tx = b.x * cs - b.y * sn;
        float ty = b.x * sn + b.y * cs;
        float2 a = r[j];
        r[j] = make_float2(a.x + tx, a.y + ty);
        if (!HOUT) r[j + 8] = make_float2(a.x - tx, a.y - ty);
    }
}

// inter-pass twiddle via recurrence: r[k1] *= exp(dir * -2*pi*i * j*k1/256)
__device__ __forceinline__ void twiddle16(float2 r[16], int j, float dir) {
    float wy, wx;
    __sincosf(dir * -0.024543692606f * (float)j, &wy, &wx);
    float cx = wx, cy = wy;
#pragma unroll
    for (int k1 = 1; k1 < 16; ++k1) {
        float2 a = r[k1];
        r[k1] = make_float2(a.x * cx - a.y * cy, a.x * cy + a.y * cx);
        float nx = cx * wx - cy * wy;
        float ny = cx * wy + cy * wx;
        cx = nx; cy = ny;
    }
}

// Full 256-pt FFT for one line handled by 16 threads (role j).
// Entry: r[BR4[n1]] = x[16*n1 + j] (odd slots unset if ZIN).
// Exit:  r[k2] = X[j + 16*k2] (k2 < 8 only if HOUT).
template<bool ZIN, bool HOUT>
__device__ __forceinline__ void fft256_pass(float2 r[16], float2* Tline,
                                            int j, float dir) {
    fft16x<ZIN, false>(r, dir);
    twiddle16(r, j, dir);
    __syncthreads();
#pragma unroll
    for (int k1 = 0; k1 < 16; ++k1) Tline[k1 * 17 + j] = r[k1];
    __syncthreads();
    float2 rr[16];
#pragma unroll
    for (int n2 = 0; n2 < 16; ++n2) rr[BR4[n2]] = Tline[j * 17 + n2];
    fft16x<false, HOUT>(rr, dir);
#pragma unroll
    for (int k = 0; k < (HOUT ? 8 : 16); ++k) r[k] = rr[k];
}

// ---------------- Pass 1: preprocess + x-FFT + x-filter ---------------------
__global__ void k_fwd_x(const float* __restrict__ in) {
    __shared__ float2 T[16][273];
    int tid = threadIdx.x;
    int j = tid & 15, ln = tid >> 4;
    unsigned h = blockIdx.x * 16 + ln, t = blockIdx.y, v = blockIdx.z;
    float g = (float)t * (1.0f / 127.0f);
    const float* src = in + (((v * 128u + t) * 128u + h) * 128u);
    float2 r[16];
#pragma unroll
    for (int n1 = 0; n1 < 8; ++n1) {
        float f = src[16 * n1 + j];
        float xx = f * g * g;
        float val = (xx > 0.0f) ? sqrtf(xx) : 0.0f;
        r[BR4[n1]] = make_float2(val, 0.0f);
    }
    fft256_pass<true, false>(r, T[ln], j, 1.0f);
    __syncthreads();
#pragma unroll
    for (int k2 = 0; k2 < 16; ++k2) T[ln][j + 17 * k2] = r[k2]; // pidx(k)=k+(k>>4)
    __syncthreads();
    __half2* __restrict__ dst = g_A + (((v * LL + t) * LL + h) * LL);
#pragma unroll
    for (int k2 = 0; k2 < 16; ++k2) {
        int k = j + 16 * k2;
        float2 a = T[ln][k + (k >> 4)];
        float2 b = make_float2(0.f, 0.f);
        if (k != 128) { int km = (k - 1) & 255; b = T[ln][km + (km >> 4)]; }
        dst[k] = f2h(make_float2(0.5f * (a.x + b.x), 0.5f * (a.y + b.y)));
    }
}

// ---------------- Pass 2: h-FFT (reads h<128) + y-filter, writes all h ------
__global__ void k_fwd_h() {
    __shared__ float2 T[16][273];
    int tid = threadIdx.x;
    int tx = tid & 15, j = tid >> 4;
    unsigned x = blockIdx.x * 16 + tx, t = blockIdx.y, v = blockIdx.z;
    unsigned base = (v * LL + t) * LL * LL + x;
    float2 r[16];
#pragma unroll
    for (int n1 = 0; n1 < 8; ++n1) {
        unsigned hh = 16 * n1 + j;
        r[BR4[n1]] = h2f(g_A[base + hh * LL]);
    }
    fft256_pass<true, false>(r, T[tx], j, 1.0f);
    __syncthreads();
#pragma unroll
    for (int k2 = 0; k2 < 16; ++k2) T[tx][j + 17 * k2] = r[k2];
    __syncthreads();
#pragma unroll
    for (int k2 = 0; k2 < 16; ++k2) {
        int k = j + 16 * k2;
        float2 a = T[tx][k + (k >> 4)];
        float2 b = make_float2(0.f, 0.f);
        if (k != 128) { int km = (k - 1) & 255; b = T[tx][km + (km >> 4)]; }
        g_A[base + (unsigned)k * LL] =
            f2h(make_float2(0.5f * (a.x + b.x), 0.5f * (a.y + b.y)));
    }
}

// ---- Pass 3 (fused): forward t-FFT -> Stolt z-resample -> inverse t-FFT ----
__global__ void k_t_samp() {
    __shared__ float2 T[16][273];
    int tid = threadIdx.x;
    int tx = tid & 15, j = tid >> 4;
    unsigned x = blockIdx.x * 16 + tx, h = blockIdx.y, v = blockIdx.z;
    unsigned base = v * LL * LL * LL + h * LL + x;

    float2 r[16];
#pragma unroll
    for (int n1 = 0; n1 < 8; ++n1) {
        unsigned tt = 16 * n1 + j;
        r[BR4[n1]] = h2f(g_A[base + tt * (LL * LL)]);
    }
    fft256_pass<true, true>(r, T[tx], j, 1.0f); // F[k], k<128, in r[0..7]

    __syncthreads();
#pragma unroll
    for (int k2 = 0; k2 < 8; ++k2) {
        int k = j + 16 * k2;
        T[tx][k + (k >> 4)] = r[k2];      // stash k<128 spectrum
    }
    __syncthreads();

    int iy = ((int)h + 128) & 255;
    int ixs = ((int)x + 128) & 255;
    float gx = (float)(ixs - 128) * (1.0f / 128.0f);
    float gy = (float)(iy - 128) * (1.0f / 128.0f);
    float rxy = 0.1024f * (gx * gx + gy * gy);

#pragma unroll
    for (int n1 = 0; n1 < 8; ++n1) {      // t = 16*n1+j < 128
        int t = 16 * n1 + j;
        float2 s = make_float2(0.f, 0.f);
        if (t >= 1) {
            float gz = (float)t * (1.0f / 128.0f);
            float q = rxy + gz * gz;       // >= (1/128)^2
            float rq = rsqrtf(q);
            float gzn = q * rq;            // sqrt(q)
            float pzf = 128.0f * gzn + 127.5f;   // >= 128.5
            int z0 = (int)pzf;
            float dz = pzf - (float)z0;
            int p0 = z0 - 128, p1 = z0 - 127;    // p0 >= 0
            float2 S0 = (p0 <= 127) ? T[tx][p0 + (p0 >> 4)] : make_float2(0.f, 0.f);
            float2 S1 = (p1 <= 127) ? T[tx][p1 + (p1 >> 4)] : make_float2(0.f, 0.f);
            float sc = gz * rq;            // ~ gz / gzn
            s = make_float2((S0.x * (1.f - dz) + S1.x * dz) * sc,
                            (S0.y * (1.f - dz) + S1.y * dz) * sc);
        }
        r[BR4[n1]] = s;                    // odd slots (t>=128) zero -> ZIN
    }
    fft256_pass<true, true>(r, T[tx], j, -1.0f);

    const float SC = 1.0f / 4096.0f;      // first chunk of 1/2^24
#pragma unroll
    for (int k2 = 0; k2 < 8; ++k2)
        g_A[base + (unsigned)(j + 16 * k2) * (LL * LL)] =
            f2h(make_float2(r[k2].x * SC, r[k2].y * SC));
}

// ---------------- Pass 4: inverse h-FFT (reads all h, writes h<128) ---------
__global__ void k_inv_h() {
    __shared__ float2 T[16][273];
    int tid = threadIdx.x;
    int tx = tid & 15, j = tid >> 4;
    unsigned x = blockIdx.x * 16 + tx, t = blockIdx.y, v = blockIdx.z;
    unsigned base = (v * LL + t) * LL * LL + x;
    float2 r[16];
#pragma unroll
    for (int n1 = 0; n1 < 16; ++n1)
        r[BR4[n1]] = h2f(g_A[base + (unsigned)(16 * n1 + j) * LL]);
    fft256_pass<false, true>(r, T[tx], j, -1.0f);
    const float SC = 1.0f / 4096.0f;      // second chunk of 1/2^24
#pragma unroll
    for (int k2 = 0; k2 < 8; ++k2)
        g_A[base + (unsigned)(j + 16 * k2) * LL] =
            f2h(make_float2(r[k2].x * SC, r[k2].y * SC));
}

// ---------------- Pass 5: inverse x-FFT + real crop ------------------------
__global__ void k_inv_x(float* __restrict__ out) {
    __shared__ float2 T[16][273];
    int tid = threadIdx.x;
    int j = tid & 15, ln = tid >> 4;
    unsigned h = blockIdx.x * 16 + ln, t = blockIdx.y, v = blockIdx.z;
    unsigned base = ((v * LL + t) * LL + h) * LL;
    float2 r[16];
#pragma unroll
    for (int n1 = 0; n1 < 16; ++n1)
        r[BR4[n1]] = h2f(g_A[base + 16 * n1 + j]);
    fft256_pass<false, true>(r, T[ln], j, -1.0f);
    float* dst = out + (((v * 128u + t) * 128u + h) * 128u);
#pragma unroll
    for (int k2 = 0; k2 < 8; ++k2)
        dst[j + 16 * k2] = r[k2].x;       // normalization fully folded upstream
}

extern "C" void kernel_launch(void* const* d_in, const int* in_sizes, int n_in,
                              void* d_out, int out_size) {
    (void)in_sizes; (void)n_in; (void)out_size;
    const float* in = (const float*)d_in[0];
    float* out = (float*)d_out;

    k_fwd_x<<<dim3(8, 128, VOLS), 256>>>(in);
    k_fwd_h<<<dim3(16, 128, VOLS), 256>>>();
    k_t_samp<<<dim3(16, 256, VOLS), 256>>>();
    k_inv_h<<<dim3(16, 128, VOLS), 256>>>();
    k_inv_x<<<dim3(8, 128, VOLS), 256>>>(out);
}